// round 1
// baseline (speedup 1.0000x reference)
#include <cuda_runtime.h>
#include <cuda_bf16.h>

// Problem constants
#define T_STEPS 4096
#define M_BATCH 512
#define D_IN    11
#define NH      51
#define G4      204          // 4*NH gate columns
#define PW1     68           // padded K for layer1 weights (62 -> 68, 68*4B = 17*16B odd -> conflict-free LDS.128)
#define PW2     108          // padded K for layer2 weights (102 -> 108, 27*16B odd)
#define A1S     64           // act1 row stride (x[11] | h1[51] | 2 pad zeros)
#define A2S     104          // act2 row stride (h1[51] | h2[51] | 2 pad zeros)
#define ROWS    4            // batch rows per block
#define THREADS 224          // 7 warps; 204 active gate-column owners
#define BLOCKS  128          // 128*4 = 512 rows

// shared-memory float offsets
#define OW1   0
#define OW2   (G4*PW1)                    // 13872
#define OA1   (OW2 + G4*PW2)              // 35904
#define OA2   (OA1 + ROWS*A1S)            // 36160
#define OGS   (OA2 + ROWS*A2S)            // 36576
#define OPO   (OGS + ROWS*G4)             // 37392
#define SMEMF (OPO + ROWS*64)             // 37648 floats
#define SMEMB (SMEMF * 4)                 // 150592 bytes

__device__ __forceinline__ float sigf(float x) {
    return __fdividef(1.0f, 1.0f + __expf(-x));
}
__device__ __forceinline__ float tanh_f(float x) {
    return __fdividef(2.0f, 1.0f + __expf(-2.0f * x)) - 1.0f;
}

__global__ void __launch_bounds__(THREADS, 1)
lstm2_persistent_kernel(const float* __restrict__ x,
                        const float* __restrict__ Wih1, const float* __restrict__ Whh1,
                        const float* __restrict__ bih1, const float* __restrict__ bhh1,
                        const float* __restrict__ Wih2, const float* __restrict__ Whh2,
                        const float* __restrict__ bih2, const float* __restrict__ bhh2,
                        const float* __restrict__ Wlin, const float* __restrict__ blin,
                        float* __restrict__ out)
{
    extern __shared__ float sm[];
    float* sW1 = sm + OW1;   // [204][68]  (x-part k<11, h-part 11..61, pad 0)
    float* sW2 = sm + OW2;   // [204][108] (h1-part k<51, h2-part 51..101, pad 0)
    float* A1  = sm + OA1;   // [4][64]
    float* A2  = sm + OA2;   // [4][104]
    float* GS  = sm + OGS;   // [4][204] gate scratch
    float* PO  = sm + OPO;   // [4][64]  output partials

    const int tid   = threadIdx.x;
    const int mbase = blockIdx.x * ROWS;

    // ---- one-time: load transposed/padded weights into shared ----
    for (int i = tid; i < G4 * PW1; i += THREADS) {
        int c = i / PW1, k = i - c * PW1;
        float v = 0.0f;
        if (k < D_IN)            v = Wih1[c * D_IN + k];
        else if (k < D_IN + NH)  v = Whh1[c * NH + (k - D_IN)];
        sW1[i] = v;
    }
    for (int i = tid; i < G4 * PW2; i += THREADS) {
        int c = i / PW2, k = i - c * PW2;
        float v = 0.0f;
        if (k < NH)            v = Wih2[c * NH + k];
        else if (k < 2 * NH)   v = Whh2[c * NH + (k - NH)];
        sW2[i] = v;
    }
    for (int i = tid; i < ROWS * A1S; i += THREADS) A1[i] = 0.0f;
    for (int i = tid; i < ROWS * A2S; i += THREADS) A2[i] = 0.0f;
    for (int i = tid; i < ROWS * 64;  i += THREADS) PO[i] = 0.0f;

    // x_0 into act1
    if (tid < ROWS * D_IN) {
        int r = tid / D_IN, k = tid - r * D_IN;
        A1[r * A1S + k] = x[(0 * M_BATCH + mbase + r) * D_IN + k];
    }

    // per-thread constants / state
    float bias1 = 0.0f, bias2 = 0.0f, wl = 0.0f;
    float c1 = 0.0f, c2 = 0.0f;
    int erow = 0, en = 0;
    if (tid < G4) {
        bias1 = bih1[tid] + bhh1[tid];
        bias2 = bih2[tid] + bhh2[tid];
        erow = tid / NH;
        en   = tid - erow * NH;
        wl   = Wlin[en];
    }
    const float bl = blin[0];

    __syncthreads();

    for (int t = 0; t < T_STEPS; ++t) {
        // prefetch x_{t+1} (latency hidden under phase S0)
        float xr = 0.0f;
        int pr = 0, pk = 0;
        if (tid < ROWS * D_IN) {
            pr = tid / D_IN;
            pk = tid - pr * D_IN;
            if (t + 1 < T_STEPS)
                xr = x[((t + 1) * M_BATCH + mbase + pr) * D_IN + pk];
        }

        // ---- S0: layer-1 gates: thread owns gate column `tid`, all 4 rows ----
        if (tid < G4) {
            float accA[ROWS], accB[ROWS];
            #pragma unroll
            for (int r = 0; r < ROWS; ++r) { accA[r] = bias1; accB[r] = 0.0f; }
            const float4* wq = reinterpret_cast<const float4*>(sW1 + tid * PW1);
            #pragma unroll
            for (int q = 0; q < A1S / 4; ++q) {        // 16 quads over k=0..63
                float4 w = wq[q];
                #pragma unroll
                for (int r = 0; r < ROWS; ++r) {
                    float4 a = reinterpret_cast<const float4*>(A1 + r * A1S)[q];
                    accA[r] = fmaf(w.x, a.x, accA[r]);
                    accB[r] = fmaf(w.y, a.y, accB[r]);
                    accA[r] = fmaf(w.z, a.z, accA[r]);
                    accB[r] = fmaf(w.w, a.w, accB[r]);
                }
            }
            #pragma unroll
            for (int r = 0; r < ROWS; ++r) GS[r * G4 + tid] = accA[r] + accB[r];
        }
        __syncthreads();

        // ---- S1: layer-1 epilogue: thread owns (erow, en) ----
        if (tid < G4) {
            float gi = GS[erow * G4 + en];
            float gf = GS[erow * G4 + NH + en];
            float gg = GS[erow * G4 + 2 * NH + en];
            float go = GS[erow * G4 + 3 * NH + en];
            c1 = sigf(gf) * c1 + sigf(gi) * tanh_f(gg);
            float h = sigf(go) * tanh_f(c1);
            A2[erow * A2S + en] = h;              // layer-2 input (this step)
            A1[erow * A1S + D_IN + en] = h;       // layer-1 h input (next step)
        }
        if (tid < ROWS * D_IN) A1[pr * A1S + pk] = xr;  // x_{t+1}
        __syncthreads();

        // ---- S2: layer-2 gates ----
        if (tid < G4) {
            float accA[ROWS], accB[ROWS];
            #pragma unroll
            for (int r = 0; r < ROWS; ++r) { accA[r] = bias2; accB[r] = 0.0f; }
            const float4* wq = reinterpret_cast<const float4*>(sW2 + tid * PW2);
            #pragma unroll
            for (int q = 0; q < A2S / 4; ++q) {        // 26 quads over k=0..103
                float4 w = wq[q];
                #pragma unroll
                for (int r = 0; r < ROWS; ++r) {
                    float4 a = reinterpret_cast<const float4*>(A2 + r * A2S)[q];
                    accA[r] = fmaf(w.x, a.x, accA[r]);
                    accB[r] = fmaf(w.y, a.y, accB[r]);
                    accA[r] = fmaf(w.z, a.z, accA[r]);
                    accB[r] = fmaf(w.w, a.w, accB[r]);
                }
            }
            #pragma unroll
            for (int r = 0; r < ROWS; ++r) GS[r * G4 + tid] = accA[r] + accB[r];
        }
        __syncthreads();

        // ---- S3: layer-2 epilogue ----
        if (tid < G4) {
            float gi = GS[erow * G4 + en];
            float gf = GS[erow * G4 + NH + en];
            float gg = GS[erow * G4 + 2 * NH + en];
            float go = GS[erow * G4 + 3 * NH + en];
            c2 = sigf(gf) * c2 + sigf(gi) * tanh_f(gg);
            float h = sigf(go) * tanh_f(c2);
            A2[erow * A2S + NH + en] = h;         // h2 for next step's layer-2 input
            PO[erow * 64 + en] = h * wl;          // output partial
        }
        __syncthreads();

        // ---- S4: output reduction, warp r handles row r ----
        if (tid < 128) {
            int r = tid >> 5, lane = tid & 31;
            float v = PO[r * 64 + lane] + PO[r * 64 + 32 + lane];  // [51..63] are zero
            #pragma unroll
            for (int off = 16; off > 0; off >>= 1)
                v += __shfl_down_sync(0xffffffffu, v, off);
            if (lane == 0)
                out[(mbase + r) * T_STEPS + t] = v + bl;
        }
        // no trailing sync needed: next-iter writes touch disjoint buffers until syncA/B
    }
}

extern "C" void kernel_launch(void* const* d_in, const int* in_sizes, int n_in,
                              void* d_out, int out_size) {
    const float* x    = (const float*)d_in[0];
    const float* Wih1 = (const float*)d_in[1];
    const float* Whh1 = (const float*)d_in[2];
    const float* bih1 = (const float*)d_in[3];
    const float* bhh1 = (const float*)d_in[4];
    const float* Wih2 = (const float*)d_in[5];
    const float* Whh2 = (const float*)d_in[6];
    const float* bih2 = (const float*)d_in[7];
    const float* bhh2 = (const float*)d_in[8];
    const float* Wlin = (const float*)d_in[9];
    const float* blin = (const float*)d_in[10];
    float* out = (float*)d_out;

    cudaFuncSetAttribute(lstm2_persistent_kernel,
                         cudaFuncAttributeMaxDynamicSharedMemorySize, SMEMB);
    lstm2_persistent_kernel<<<BLOCKS, THREADS, SMEMB>>>(
        x, Wih1, Whh1, bih1, bhh1, Wih2, Whh2, bih2, bhh2, Wlin, blin, out);
}

// round 3
// speedup vs baseline: 1.0305x; 1.0305x over previous
#include <cuda_runtime.h>
#include <cuda_bf16.h>

// Problem constants
#define T_STEPS 4096
#define M_BATCH 512
#define D_IN    11
#define NH      51
#define G4      204          // 4*NH gate columns
#define PW1     68           // padded K layer1 (x[11]|h1[51], pad->68; 17*16B odd stride: conflict-free)
#define PW2     108          // padded K layer2 (h1[51]|h2[51], pad->108; 27*16B odd stride)
#define A1S     64           // act1 row stride
#define A2S     104          // act2 row stride
#define ROWS    4            // batch rows per block
#define THREADS 512          // 16 warps; 2-way K-split over 204 gate columns
#define BLOCKS  128          // 128*4 = 512 rows

// shared-memory float offsets
#define OW1   0
#define OW2   (G4*PW1)                    // 13872
#define OA1   (OW2 + G4*PW2)              // 35904
#define OA2   (OA1 + ROWS*A1S)            // 36160
#define OGA   (OA2 + ROWS*A2S)            // 36576
#define OGB   (OGA + ROWS*G4)             // 37392
#define OPO   (OGB + ROWS*G4)             // 38208
#define SMEMF (OPO + ROWS*64)             // 38464 floats
#define SMEMB (SMEMF * 4)                 // 153856 bytes

__device__ __forceinline__ float sigf(float x) {
    return __fdividef(1.0f, 1.0f + __expf(-x));
}
__device__ __forceinline__ float tanh_f(float x) {
    return __fdividef(2.0f, 1.0f + __expf(-2.0f * x)) - 1.0f;
}

// packed 2xfp32 FMA (Blackwell f32x2 pipe): d = a*b + c per 32-bit lane
__device__ __forceinline__ unsigned long long fma2(unsigned long long a,
                                                   unsigned long long b,
                                                   unsigned long long c) {
    unsigned long long d;
    asm("fma.rn.f32x2 %0, %1, %2, %3;" : "=l"(d) : "l"(a), "l"(b), "l"(c));
    return d;
}
__device__ __forceinline__ unsigned long long pack2(float lo, float hi) {
    unsigned long long r;
    asm("mov.b64 %0, {%1, %2};" : "=l"(r) : "f"(lo), "f"(hi));
    return r;
}
__device__ __forceinline__ float sum2(unsigned long long v) {
    float lo, hi;
    asm("mov.b64 {%0, %1}, %2;" : "=f"(lo), "=f"(hi) : "l"(v));
    return lo + hi;
}

__global__ void __launch_bounds__(THREADS, 1)
lstm2_persistent_kernel(const float* __restrict__ x,
                        const float* __restrict__ Wih1, const float* __restrict__ Whh1,
                        const float* __restrict__ bih1, const float* __restrict__ bhh1,
                        const float* __restrict__ Wih2, const float* __restrict__ Whh2,
                        const float* __restrict__ bih2, const float* __restrict__ bhh2,
                        const float* __restrict__ Wlin, const float* __restrict__ blin,
                        float* __restrict__ out)
{
    extern __shared__ float sm[];
    float* sW1 = sm + OW1;   // [204][68]
    float* sW2 = sm + OW2;   // [204][108]
    float* A1  = sm + OA1;   // [4][64]   x[11] | h1[51] | pad
    float* A2  = sm + OA2;   // [4][104]  h1[51] | h2[51] | pad
    float* GSa = sm + OGA;   // [4][204]  K-half-0 partials
    float* GSb = sm + OGB;   // [4][204]  K-half-1 partials
    float* PO  = sm + OPO;   // [4][64]   output partials

    const int tid   = threadIdx.x;
    const int mbase = blockIdx.x * ROWS;
    const int hf    = tid >> 8;        // K-half (0/1)
    const int cidx  = tid & 255;       // gate column candidate
    const bool gate_active = (cidx < G4);

    // ---- one-time: transposed/padded weights into shared ----
    for (int i = tid; i < G4 * PW1; i += THREADS) {
        int c = i / PW1, k = i - c * PW1;
        float v = 0.0f;
        if (k < D_IN)            v = Wih1[c * D_IN + k];
        else if (k < D_IN + NH)  v = Whh1[c * NH + (k - D_IN)];
        sW1[i] = v;
    }
    for (int i = tid; i < G4 * PW2; i += THREADS) {
        int c = i / PW2, k = i - c * PW2;
        float v = 0.0f;
        if (k < NH)            v = Wih2[c * NH + k];
        else if (k < 2 * NH)   v = Whh2[c * NH + (k - NH)];
        sW2[i] = v;
    }
    for (int i = tid; i < ROWS * A1S; i += THREADS) A1[i] = 0.0f;
    for (int i = tid; i < ROWS * A2S; i += THREADS) A2[i] = 0.0f;
    for (int i = tid; i < ROWS * 64;  i += THREADS) PO[i] = 0.0f;

    if (tid < ROWS * D_IN) {
        int r = tid / D_IN, k = tid - r * D_IN;
        A1[r * A1S + k] = x[(0 * M_BATCH + mbase + r) * D_IN + k];
    }

    // per-thread constants / state (bias only added by K-half-0 thread)
    float bias1 = 0.0f, bias2 = 0.0f, wl = 0.0f;
    float c1 = 0.0f, c2 = 0.0f;
    int erow = 0, en = 0;
    if (tid < G4) {                       // half-0 gate threads double as epilogue threads
        bias1 = bih1[tid] + bhh1[tid];
        bias2 = bih2[tid] + bhh2[tid];
        erow = tid / NH;
        en   = tid - erow * NH;
        wl   = Wlin[en];
    }
    const float bl = blin[0];
    float* GH = hf ? GSb : GSa;

    __syncthreads();

    for (int t = 0; t < T_STEPS; ++t) {
        // prefetch x_{t+1} (hidden under S0)
        float xr = 0.0f;
        int pr = 0, pk = 0;
        if (tid < ROWS * D_IN) {
            pr = tid / D_IN;
            pk = tid - pr * D_IN;
            if (t + 1 < T_STEPS)
                xr = x[((t + 1) * M_BATCH + mbase + pr) * D_IN + pk];
        }

        // ---- S0: layer-1 gates, 2-way K-split, f32x2 k-pair FMAs ----
        if (gate_active) {
            unsigned long long acc[ROWS];
            #pragma unroll
            for (int r = 0; r < ROWS; ++r) acc[r] = pack2(bias1, 0.0f);
            const int q0 = hf * 8;                        // quads [0,8) / [8,16)
            const ulonglong2* wq = reinterpret_cast<const ulonglong2*>(sW1 + cidx * PW1);
            #pragma unroll
            for (int q = 0; q < 8; ++q) {
                ulonglong2 w = wq[q0 + q];
                #pragma unroll
                for (int r = 0; r < ROWS; ++r) {
                    ulonglong2 a = reinterpret_cast<const ulonglong2*>(A1 + r * A1S)[q0 + q];
                    acc[r] = fma2(w.x, a.x, acc[r]);
                    acc[r] = fma2(w.y, a.y, acc[r]);
                }
            }
            #pragma unroll
            for (int r = 0; r < ROWS; ++r) GH[r * G4 + cidx] = sum2(acc[r]);
        }
        __syncthreads();

        // ---- S1: layer-1 epilogue (thread = (row, n)) ----
        if (tid < G4) {
            float gi = GSa[erow * G4 + en]          + GSb[erow * G4 + en];
            float gf = GSa[erow * G4 + NH + en]     + GSb[erow * G4 + NH + en];
            float gg = GSa[erow * G4 + 2 * NH + en] + GSb[erow * G4 + 2 * NH + en];
            float go = GSa[erow * G4 + 3 * NH + en] + GSb[erow * G4 + 3 * NH + en];
            c1 = sigf(gf) * c1 + sigf(gi) * tanh_f(gg);
            float h = sigf(go) * tanh_f(c1);
            A2[erow * A2S + en] = h;              // layer-2 input (this step)
            A1[erow * A1S + D_IN + en] = h;       // layer-1 h input (next step)
        }
        if (tid < ROWS * D_IN) A1[pr * A1S + pk] = xr;  // x_{t+1}
        __syncthreads();

        // ---- S2: layer-2 gates ----
        if (gate_active) {
            unsigned long long acc[ROWS];
            #pragma unroll
            for (int r = 0; r < ROWS; ++r) acc[r] = pack2(bias2, 0.0f);
            const int q0 = hf * 13;                       // quads [0,13) / [13,26)
            const ulonglong2* wq = reinterpret_cast<const ulonglong2*>(sW2 + cidx * PW2);
            #pragma unroll
            for (int q = 0; q < 13; ++q) {
                ulonglong2 w = wq[q0 + q];
                #pragma unroll
                for (int r = 0; r < ROWS; ++r) {
                    ulonglong2 a = reinterpret_cast<const ulonglong2*>(A2 + r * A2S)[q0 + q];
                    acc[r] = fma2(w.x, a.x, acc[r]);
                    acc[r] = fma2(w.y, a.y, acc[r]);
                }
            }
            #pragma unroll
            for (int r = 0; r < ROWS; ++r) GH[r * G4 + cidx] = sum2(acc[r]);
        }
        __syncthreads();

        // ---- S3: layer-2 epilogue ----
        if (tid < G4) {
            float gi = GSa[erow * G4 + en]          + GSb[erow * G4 + en];
            float gf = GSa[erow * G4 + NH + en]     + GSb[erow * G4 + NH + en];
            float gg = GSa[erow * G4 + 2 * NH + en] + GSb[erow * G4 + 2 * NH + en];
            float go = GSa[erow * G4 + 3 * NH + en] + GSb[erow * G4 + 3 * NH + en];
            c2 = sigf(gf) * c2 + sigf(gi) * tanh_f(gg);
            float h = sigf(go) * tanh_f(c2);
            A2[erow * A2S + NH + en] = h;         // h2 for next step
            PO[erow * 64 + en] = h * wl;          // output partial
        }
        __syncthreads();

        // ---- S4: output reduction, warp r handles row r ----
        if (tid < 128) {
            int r = tid >> 5, lane = tid & 31;
            float v = PO[r * 64 + lane] + PO[r * 64 + 32 + lane];  // [51..63] zero
            #pragma unroll
            for (int off = 16; off > 0; off >>= 1)
                v += __shfl_down_sync(0xffffffffu, v, off);
            if (lane == 0)
                out[(mbase + r) * T_STEPS + t] = v + bl;
        }
        // next-iter S0 writes GSa/GSb only after the S3 sync; PO re-written after S3 sync next iter
    }
}

extern "C" void kernel_launch(void* const* d_in, const int* in_sizes, int n_in,
                              void* d_out, int out_size) {
    const float* x    = (const float*)d_in[0];
    const float* Wih1 = (const float*)d_in[1];
    const float* Whh1 = (const float*)d_in[2];
    const float* bih1 = (const float*)d_in[3];
    const float* bhh1 = (const float*)d_in[4];
    const float* Wih2 = (const float*)d_in[5];
    const float* Whh2 = (const float*)d_in[6];
    const float* bih2 = (const float*)d_in[7];
    const float* bhh2 = (const float*)d_in[8];
    const float* Wlin = (const float*)d_in[9];
    const float* blin = (const float*)d_in[10];
    float* out = (float*)d_out;

    cudaFuncSetAttribute(lstm2_persistent_kernel,
                         cudaFuncAttributeMaxDynamicSharedMemorySize, SMEMB);
    lstm2_persistent_kernel<<<BLOCKS, THREADS, SMEMB>>>(
        x, Wih1, Whh1, bih1, bhh1, Wih2, Whh2, bih2, bhh2, Wlin, blin, out);
}